// round 12
// baseline (speedup 1.0000x reference)
#include <cuda_runtime.h>
#include <math.h>

#define SDIM   256
#define MDIM   64
#define SETUP_BLOCKS 8
#define GRID   592           // 148 SMs x 4 blocks/SM: one fully resident wave
#define MAXIT  32            // >= ceil(ceil(V/4) / (GRID*8)) = 27 for V=500000

struct GConst {
    float k, logk, r, T1, T2, T3;
};

__device__ GConst g_c[2];
__device__ double g_sum = 0.0;
__device__ double g_acc[4] = {0.0, 0.0, 0.0, 0.0};
__device__ unsigned g_tick0 = 0;   // setup ticket
__device__ unsigned g_tick1 = 0;   // exit ticket
__device__ unsigned g_ready = 0;   // constants-ready flag

__device__ __forceinline__ float group_term(float k, float logk, float r,
                                            float T1, float T2, float T3,
                                            float dot, float y)
{
    float t  = k * __expf(dot);
    float l1 = log1pf(t);
    int iy = (int)y;
    float T = (iy == 1) ? T1 : (iy == 2) ? T2 : (iy == 3) ? T3 : 0.0f;
    return fmaf(-(r + y), l1, fmaf(y, logk + dot, T));
}

__device__ __forceinline__ float2 dots_for_row(const float4 a, const float4 b,
                                               const float4 w0a, const float4 w0b,
                                               const float4 w1a, const float4 w1b)
{
    float p0 = a.x*w0a.x + a.y*w0a.y + a.z*w0a.z + a.w*w0a.w
             + b.x*w0b.x + b.y*w0b.y + b.z*w0b.z + b.w*w0b.w;
    float p1 = a.x*w1a.x + a.y*w1a.y + a.z*w1a.z + a.w*w1a.w
             + b.x*w1b.x + b.y*w1b.y + b.z*w1b.z + b.w*w1b.w;
    return make_float2(p0, p1);
}

__device__ __forceinline__ float merge_pair(float A, float B, int o)
{
    float send = (threadIdx.x & o) ? A : B;
    float keep = (threadIdx.x & o) ? B : A;
    return keep + __shfl_xor_sync(0xffffffff, send, o);
}

// ---------------------------------------------------------------------------
// Single fused kernel. Blocks 0..7: inline setup prologue. All blocks then run
// the frozen streaming loop, stashing (dot, y) pairs to smem instead of
// evaluating terms. Ready-wait + all epilogues happen AFTER the loop.
// ---------------------------------------------------------------------------
__global__ void __launch_bounds__(256, 4)
nb_fused_kernel(const float* __restrict__ X,
                const float* __restrict__ mod0,
                const float* __restrict__ mod1,
                const float* __restrict__ y0,
                const float* __restrict__ y1,
                const float* __restrict__ W,
                const float* __restrict__ wm,
                const float* __restrict__ ods,
                float* __restrict__ out,
                int V, int nstudy)
{
    const int tid  = threadIdx.x;
    const int lane = tid & 31;
    const int widb = tid >> 5;

    __shared__ float sdots[8][MAXIT * 8];
    __shared__ float sy[8][MAXIT * 8];
    __shared__ double sred[8];

    // ---------------- inline setup prologue: blocks 0..7 -------------------
    if (blockIdx.x < SETUP_BLOCKS) {
        __shared__ float swm[MDIM];
        if (tid < MDIM) swm[tid] = wm[tid];
        __syncthreads();

        const int s = blockIdx.x * 256 + tid;   // one study per thread
        double m0 = 0.0, m20 = 0.0, m1 = 0.0, m21 = 0.0;
        if (s < nstudy) {
            const float4* r0 = (const float4*)(mod0 + (size_t)s * MDIM);
            const float4* r1 = (const float4*)(mod1 + (size_t)s * MDIM);
            float d0 = 0.f, d1 = 0.f;
            #pragma unroll
            for (int j = 0; j < MDIM / 4; ++j) {
                float4 a = r0[j], b = r1[j];
                const float4 w = ((const float4*)swm)[j];
                d0 += a.x*w.x + a.y*w.y + a.z*w.z + a.w*w.w;
                d1 += b.x*w.x + b.y*w.y + b.z*w.z + b.w*w.w;
            }
            float e0 = expf(d0), e1 = expf(d1);
            m0  = (double)e0;  m20 = (double)e0 * (double)e0;
            m1  = (double)e1;  m21 = (double)e1 * (double)e1;
        }
        #pragma unroll
        for (int off = 16; off > 0; off >>= 1) {
            m0  += __shfl_xor_sync(0xffffffff, m0,  off);
            m20 += __shfl_xor_sync(0xffffffff, m20, off);
            m1  += __shfl_xor_sync(0xffffffff, m1,  off);
            m21 += __shfl_xor_sync(0xffffffff, m21, off);
        }
        if (lane == 0) {
            atomicAdd(&g_acc[0], m0);
            atomicAdd(&g_acc[1], m20);
            atomicAdd(&g_acc[2], m1);
            atomicAdd(&g_acc[3], m21);
        }
        __threadfence();
        __syncthreads();

        if (tid == 0) {
            unsigned t = atomicAdd(&g_tick0, 1u);
            if (t == SETUP_BLOCKS - 1) {
                __threadfence();
                double sm[2], sm2[2];
                sm[0]  = atomicAdd(&g_acc[0], 0.0);
                sm2[0] = atomicAdd(&g_acc[1], 0.0);
                sm[1]  = atomicAdd(&g_acc[2], 0.0);
                sm2[1] = atomicAdd(&g_acc[3], 0.0);
                #pragma unroll
                for (int g = 0; g < 2; ++g) {
                    float  so = ods[g];
                    double vv = 1.0 / ((double)so * (double)so);
                    double r  = vv * sm[g] * sm[g] / sm2[g];
                    double k  = sm2[g] / (vv * sm[g]);
                    float rf = (float)r;
                    float T1 = logf(rf);
                    float T2 = T1 + logf(rf + 1.0f) - 0.6931471805599453f;
                    float T3 = T2 + logf(rf + 2.0f) - 1.0986122886681098f;
                    g_c[g].k = (float)k;
                    g_c[g].logk = logf((float)k);
                    g_c[g].r = rf;
                    g_c[g].T1 = T1;
                    g_c[g].T2 = T2;
                    g_c[g].T3 = T3;
                }
                g_sum = 0.0;
                g_acc[0] = 0.0; g_acc[1] = 0.0; g_acc[2] = 0.0; g_acc[3] = 0.0;
                g_tick0 = 0;
                __threadfence();
                atomicExch(&g_ready, 1u);   // release
            }
        }
    }

    // ---------------- streaming loop (frozen body, epilogue -> smem) -------
    const int nwb    = blockDim.x >> 5;
    const int gwarp  = blockIdx.x * nwb + widb;
    const int nwarps = gridDim.x * nwb;

    const float4* W4 = (const float4*)W;
    const float4 w0a = W4[lane],      w0b = W4[lane + 32];
    const float4 w1a = W4[64 + lane], w1b = W4[96 + lane];

    const bool odd = (lane & 1);
    const float* yp = odd ? y1 : y0;

    const int ngroups = (V + 3) >> 2;
    int it = 0;
    for (int g = gwarp; g < ngroups; g += nwarps) {
        const int v = g << 2;
        const int r1 = min(v + 1, V - 1);
        const int r2 = min(v + 2, V - 1);
        const int r3 = min(v + 3, V - 1);
        const float4* x0 = (const float4*)(X + (size_t)v  * SDIM);
        const float4* x1 = (const float4*)(X + (size_t)r1 * SDIM);
        const float4* x2 = (const float4*)(X + (size_t)r2 * SDIM);
        const float4* x3 = (const float4*)(X + (size_t)r3 * SDIM);

        float4 a0 = __ldcs(x0 + lane), b0 = __ldcs(x0 + lane + 32);
        float4 a1 = __ldcs(x1 + lane), b1 = __ldcs(x1 + lane + 32);
        float4 a2 = __ldcs(x2 + lane), b2 = __ldcs(x2 + lane + 32);
        float4 a3 = __ldcs(x3 + lane), b3 = __ldcs(x3 + lane + 32);

        float ylv = 0.f;
        if (lane < 8) {
            int idx = v + (lane >> 1);
            if (idx < V) ylv = __ldcs(yp + idx);
        }

        float2 d0 = dots_for_row(a0, b0, w0a, w0b, w1a, w1b);
        float2 d1 = dots_for_row(a1, b1, w0a, w0b, w1a, w1b);
        float2 d2 = dots_for_row(a2, b2, w0a, w0b, w1a, w1b);
        float2 d3 = dots_for_row(a3, b3, w0a, w0b, w1a, w1b);

        float e0 = merge_pair(d0.x, d0.y, 1);
        float e1 = merge_pair(d1.x, d1.y, 1);
        float e2 = merge_pair(d2.x, d2.y, 1);
        float e3 = merge_pair(d3.x, d3.y, 1);
        float f0 = merge_pair(e0, e1, 2);
        float f1 = merge_pair(e2, e3, 2);
        float gg = merge_pair(f0, f1, 4);
        gg += __shfl_xor_sync(0xffffffff, gg, 8);
        gg += __shfl_xor_sync(0xffffffff, gg, 16);

        // stash (dot, y) for deferred epilogue: 2 STS, lanes 0-7 only
        if (lane < 8 && it < MAXIT) {
            sdots[widb][it * 8 + lane] = gg;
            sy[widb][it * 8 + lane]    = ylv;
        }
        ++it;
    }

    // ---------------- wait for constants (always already set by now) -------
    if (lane == 0) {
        while (atomicAdd(&g_ready, 0u) == 0u) __nanosleep(32);
    }
    __syncwarp();
    __threadfence();   // acquire: order g_c reads after the flag

    const GConst c0 = g_c[0];
    const GConst c1 = g_c[1];
    const float sk    = odd ? c1.k    : c0.k;
    const float slogk = odd ? c1.logk : c0.logk;
    const float sr    = odd ? c1.r    : c0.r;
    const float sT1   = odd ? c1.T1   : c0.T1;
    const float sT2   = odd ? c1.T2   : c0.T2;
    const float sT3   = odd ? c1.T3   : c0.T3;

    // ---------------- deferred epilogues (same per-warp FP order) ----------
    double acc = 0.0;
    for (int i = 0; i < it; ++i) {
        float term = 0.f;
        const int v = (gwarp + i * nwarps) << 2;
        if (lane < 8 && (v + (lane >> 1)) < V) {
            float dot = sdots[widb][i * 8 + lane];
            float yy  = sy[widb][i * 8 + lane];
            term = group_term(sk, slogk, sr, sT1, sT2, sT3, dot, yy);
        }
        term += __shfl_xor_sync(0xffffffff, term, 1);
        term += __shfl_xor_sync(0xffffffff, term, 2);
        term += __shfl_xor_sync(0xffffffff, term, 4);
        if (lane == 0) acc += (double)term;
    }

    // ---------------- global reduce + output + flag reset ------------------
    if (lane == 0) sred[widb] = acc;
    __syncthreads();
    if (tid == 0) {
        double t = 0.0;
        for (int i = 0; i < nwb; ++i) t += sred[i];
        atomicAdd(&g_sum, t);
        __threadfence();
        unsigned tk = atomicAdd(&g_tick1, 1u);
        if (tk == gridDim.x - 1) {
            __threadfence();
            double total = atomicAdd(&g_sum, 0.0);
            out[0] = (float)(-total);
            g_tick1 = 0;
            g_ready = 0;
            __threadfence();
        }
    }
}

extern "C" void kernel_launch(void* const* d_in, const int* in_sizes, int n_in,
                              void* d_out, int out_size)
{
    const float* X    = (const float*)d_in[0]; // [V,256]
    const float* mod0 = (const float*)d_in[1]; // [S,64]
    const float* mod1 = (const float*)d_in[2];
    const float* y0   = (const float*)d_in[3]; // [V]
    const float* y1   = (const float*)d_in[4];
    const float* W    = (const float*)d_in[5]; // [2,256]
    const float* wm   = (const float*)d_in[6]; // [64]
    const float* ods  = (const float*)d_in[7]; // [2]
    float* out = (float*)d_out;

    const int V = in_sizes[0] / SDIM;
    const int S = in_sizes[1] / MDIM;

    nb_fused_kernel<<<GRID, 256>>>(X, mod0, mod1, y0, y1, W, wm, ods, out, V, S);
}

// round 13
// speedup vs baseline: 1.1992x; 1.1992x over previous
#include <cuda_runtime.h>
#include <math.h>

#define SDIM   256
#define MDIM   64
#define SETUP_BLOCKS 8
#define GRID   592          // 148 SMs x 4 blocks/SM: one fully resident wave

struct GConst {
    float k, logk, r, T1, T2, T3;
};

__device__ GConst g_c[2];
__device__ double g_sum = 0.0;
__device__ double g_acc[4] = {0.0, 0.0, 0.0, 0.0};
__device__ unsigned g_tick0 = 0;   // setup ticket
__device__ unsigned g_tick1 = 0;   // exit ticket
__device__ volatile unsigned g_ready = 0;   // constants-ready flag (plain ld/st)

__device__ __forceinline__ float group_term(float k, float logk, float r,
                                            float T1, float T2, float T3,
                                            float dot, float y)
{
    float t  = k * __expf(dot);
    float l1 = log1pf(t);
    int iy = (int)y;
    float T = (iy == 1) ? T1 : (iy == 2) ? T2 : (iy == 3) ? T3 : 0.0f;
    return fmaf(-(r + y), l1, fmaf(y, logk + dot, T));
}

__device__ __forceinline__ float2 dots_for_row(const float4 a, const float4 b,
                                               const float4 w0a, const float4 w0b,
                                               const float4 w1a, const float4 w1b)
{
    float p0 = a.x*w0a.x + a.y*w0a.y + a.z*w0a.z + a.w*w0a.w
             + b.x*w0b.x + b.y*w0b.y + b.z*w0b.z + b.w*w0b.w;
    float p1 = a.x*w1a.x + a.y*w1a.y + a.z*w1a.z + a.w*w1a.w
             + b.x*w1b.x + b.y*w1b.y + b.z*w1b.z + b.w*w1b.w;
    return make_float2(p0, p1);
}

__device__ __forceinline__ float merge_pair(float A, float B, int o)
{
    float send = (threadIdx.x & o) ? A : B;
    float keep = (threadIdx.x & o) ? B : A;
    return keep + __shfl_xor_sync(0xffffffff, send, o);
}

// ---------------------------------------------------------------------------
// Single fused kernel, one resident wave. Blocks 0..7: inline setup prologue.
// All blocks: volatile-load spin (no atomic serialization), then the frozen
// R9 streaming loop with constants in registers.
// ---------------------------------------------------------------------------
__global__ void __launch_bounds__(256, 4)
nb_fused_kernel(const float* __restrict__ X,
                const float* __restrict__ mod0,
                const float* __restrict__ mod1,
                const float* __restrict__ y0,
                const float* __restrict__ y1,
                const float* __restrict__ W,
                const float* __restrict__ wm,
                const float* __restrict__ ods,
                float* __restrict__ out,
                int V, int nstudy)
{
    const int tid  = threadIdx.x;
    const int lane = tid & 31;
    const int widb = tid >> 5;

    // ---------------- inline setup prologue: blocks 0..7 -------------------
    if (blockIdx.x < SETUP_BLOCKS) {
        __shared__ float swm[MDIM];
        if (tid < MDIM) swm[tid] = wm[tid];
        __syncthreads();

        const int s = blockIdx.x * 256 + tid;   // one study per thread
        double m0 = 0.0, m20 = 0.0, m1 = 0.0, m21 = 0.0;
        if (s < nstudy) {
            const float4* r0 = (const float4*)(mod0 + (size_t)s * MDIM);
            const float4* r1 = (const float4*)(mod1 + (size_t)s * MDIM);
            float d0 = 0.f, d1 = 0.f;
            #pragma unroll
            for (int j = 0; j < MDIM / 4; ++j) {
                float4 a = r0[j], b = r1[j];
                const float4 w = ((const float4*)swm)[j];
                d0 += a.x*w.x + a.y*w.y + a.z*w.z + a.w*w.w;
                d1 += b.x*w.x + b.y*w.y + b.z*w.z + b.w*w.w;
            }
            float e0 = expf(d0), e1 = expf(d1);
            m0  = (double)e0;  m20 = (double)e0 * (double)e0;
            m1  = (double)e1;  m21 = (double)e1 * (double)e1;
        }
        #pragma unroll
        for (int off = 16; off > 0; off >>= 1) {
            m0  += __shfl_xor_sync(0xffffffff, m0,  off);
            m20 += __shfl_xor_sync(0xffffffff, m20, off);
            m1  += __shfl_xor_sync(0xffffffff, m1,  off);
            m21 += __shfl_xor_sync(0xffffffff, m21, off);
        }
        if (lane == 0) {
            atomicAdd(&g_acc[0], m0);
            atomicAdd(&g_acc[1], m20);
            atomicAdd(&g_acc[2], m1);
            atomicAdd(&g_acc[3], m21);
        }
        __threadfence();
        __syncthreads();

        if (tid == 0) {
            unsigned t = atomicAdd(&g_tick0, 1u);
            if (t == SETUP_BLOCKS - 1) {
                __threadfence();
                double sm[2], sm2[2];
                sm[0]  = atomicAdd(&g_acc[0], 0.0);
                sm2[0] = atomicAdd(&g_acc[1], 0.0);
                sm[1]  = atomicAdd(&g_acc[2], 0.0);
                sm2[1] = atomicAdd(&g_acc[3], 0.0);
                #pragma unroll
                for (int g = 0; g < 2; ++g) {
                    float  so = ods[g];
                    double vv = 1.0 / ((double)so * (double)so);
                    double r  = vv * sm[g] * sm[g] / sm2[g];
                    double k  = sm2[g] / (vv * sm[g]);
                    float rf = (float)r;
                    float T1 = logf(rf);
                    float T2 = T1 + logf(rf + 1.0f) - 0.6931471805599453f;
                    float T3 = T2 + logf(rf + 2.0f) - 1.0986122886681098f;
                    g_c[g].k = (float)k;
                    g_c[g].logk = logf((float)k);
                    g_c[g].r = rf;
                    g_c[g].T1 = T1;
                    g_c[g].T2 = T2;
                    g_c[g].T3 = T3;
                }
                g_sum = 0.0;
                g_acc[0] = 0.0; g_acc[1] = 0.0; g_acc[2] = 0.0; g_acc[3] = 0.0;
                g_tick0 = 0;
                __threadfence();     // release: g_c visible before flag
                g_ready = 1u;        // plain volatile store
            }
        }
    }

    // ---------------- ready-wait: plain volatile loads, one per block ------
    if (tid == 0) {
        while (g_ready == 0u) __nanosleep(64);
    }
    __syncthreads();
    __threadfence();   // acquire

    // ---------------- streaming loop (frozen R9 body) ----------------------
    const int nwb    = blockDim.x >> 5;
    const int gwarp  = blockIdx.x * nwb + widb;
    const int nwarps = gridDim.x * nwb;

    const float4* W4 = (const float4*)W;
    const float4 w0a = W4[lane],      w0b = W4[lane + 32];
    const float4 w1a = W4[64 + lane], w1b = W4[96 + lane];

    const GConst c0 = g_c[0];
    const GConst c1 = g_c[1];
    const bool odd = (lane & 1);
    const float sk    = odd ? c1.k    : c0.k;
    const float slogk = odd ? c1.logk : c0.logk;
    const float sr    = odd ? c1.r    : c0.r;
    const float sT1   = odd ? c1.T1   : c0.T1;
    const float sT2   = odd ? c1.T2   : c0.T2;
    const float sT3   = odd ? c1.T3   : c0.T3;
    const float* yp   = odd ? y1 : y0;

    double acc = 0.0;

    const int ngroups = (V + 3) >> 2;
    for (int g = gwarp; g < ngroups; g += nwarps) {
        const int v = g << 2;
        const int r1 = min(v + 1, V - 1);
        const int r2 = min(v + 2, V - 1);
        const int r3 = min(v + 3, V - 1);
        const float4* x0 = (const float4*)(X + (size_t)v  * SDIM);
        const float4* x1 = (const float4*)(X + (size_t)r1 * SDIM);
        const float4* x2 = (const float4*)(X + (size_t)r2 * SDIM);
        const float4* x3 = (const float4*)(X + (size_t)r3 * SDIM);

        float4 a0 = __ldcs(x0 + lane), b0 = __ldcs(x0 + lane + 32);
        float4 a1 = __ldcs(x1 + lane), b1 = __ldcs(x1 + lane + 32);
        float4 a2 = __ldcs(x2 + lane), b2 = __ldcs(x2 + lane + 32);
        float4 a3 = __ldcs(x3 + lane), b3 = __ldcs(x3 + lane + 32);

        float ylv = 0.f;
        if (lane < 8) {
            int idx = v + (lane >> 1);
            if (idx < V) ylv = __ldcs(yp + idx);
        }

        float2 d0 = dots_for_row(a0, b0, w0a, w0b, w1a, w1b);
        float2 d1 = dots_for_row(a1, b1, w0a, w0b, w1a, w1b);
        float2 d2 = dots_for_row(a2, b2, w0a, w0b, w1a, w1b);
        float2 d3 = dots_for_row(a3, b3, w0a, w0b, w1a, w1b);

        float e0 = merge_pair(d0.x, d0.y, 1);
        float e1 = merge_pair(d1.x, d1.y, 1);
        float e2 = merge_pair(d2.x, d2.y, 1);
        float e3 = merge_pair(d3.x, d3.y, 1);
        float f0 = merge_pair(e0, e1, 2);
        float f1 = merge_pair(e2, e3, 2);
        float gg = merge_pair(f0, f1, 4);
        gg += __shfl_xor_sync(0xffffffff, gg, 8);
        gg += __shfl_xor_sync(0xffffffff, gg, 16);

        float term = 0.f;
        if (lane < 8 && (v + (lane >> 1)) < V)
            term = group_term(sk, slogk, sr, sT1, sT2, sT3, gg, ylv);

        term += __shfl_xor_sync(0xffffffff, term, 1);
        term += __shfl_xor_sync(0xffffffff, term, 2);
        term += __shfl_xor_sync(0xffffffff, term, 4);
        if (lane == 0) acc += (double)term;
    }

    // ---------------- global reduce + output + flag reset ------------------
    __shared__ double sred[8];
    if (lane == 0) sred[widb] = acc;
    __syncthreads();
    if (tid == 0) {
        double t = 0.0;
        for (int i = 0; i < nwb; ++i) t += sred[i];
        atomicAdd(&g_sum, t);
        __threadfence();
        unsigned tk = atomicAdd(&g_tick1, 1u);
        if (tk == gridDim.x - 1) {
            __threadfence();
            double total = atomicAdd(&g_sum, 0.0);
            out[0] = (float)(-total);
            g_tick1 = 0;
            g_ready = 0;
            __threadfence();
        }
    }
}

extern "C" void kernel_launch(void* const* d_in, const int* in_sizes, int n_in,
                              void* d_out, int out_size)
{
    const float* X    = (const float*)d_in[0]; // [V,256]
    const float* mod0 = (const float*)d_in[1]; // [S,64]
    const float* mod1 = (const float*)d_in[2];
    const float* y0   = (const float*)d_in[3]; // [V]
    const float* y1   = (const float*)d_in[4];
    const float* W    = (const float*)d_in[5]; // [2,256]
    const float* wm   = (const float*)d_in[6]; // [64]
    const float* ods  = (const float*)d_in[7]; // [2]
    float* out = (float*)d_out;

    const int V = in_sizes[0] / SDIM;
    const int S = in_sizes[1] / MDIM;

    nb_fused_kernel<<<GRID, 256>>>(X, mod0, mod1, y0, y1, W, wm, ods, out, V, S);
}